// round 4
// baseline (speedup 1.0000x reference)
#include <cuda_runtime.h>
#include <cuda_bf16.h>

#define NPTS    500000
#define C_OUT   64
#define D_IN    208
#define GRID_H  256
#define GRID_W  256
#define NCELL   (GRID_H * GRID_W)
#define BLK     256                       // points per CTA
#define NTH     512
#define NBLK    ((NPTS + BLK - 1) / BLK)
#define KC      26                        // K-chunk (8 * 26 = 208)
#define HP      260                       // padded point-stride for H rows

// shared float offsets
#define OW1  0            // 208*64        = 13312
#define OW2D 13312        // 64*128 (dup)  = 8192
#define OXD  21504        // 26*512 (dup)  = 13312
#define OH   34816        // 64*260        = 16640
#define OB1  51456
#define OG   51520
#define OB   51584
#define OB2  51648
#define OFQ  51712        // 32
#define OFL  51744        // 256 ints
#define SMF  52000
#define SMB  (SMF * 4)

__device__ float g_accum[NCELL * C_OUT];   // cell-major scratch [cell][ch]
__device__ float g_counts[NCELL];

__device__ __forceinline__ void fma2(unsigned long long& d, unsigned long long a,
                                     unsigned long long b) {
    asm("fma.rn.f32x2 %0, %1, %2, %0;" : "+l"(d) : "l"(a), "l"(b));
}
__device__ __forceinline__ float2 up2(unsigned long long a) {
    float2 r;
    asm("mov.b64 {%0, %1}, %2;" : "=f"(r.x), "=f"(r.y) : "l"(a));
    return r;
}
__device__ __forceinline__ void red4(float* p, float a, float b, float c, float d) {
    asm volatile("red.global.add.v4.f32 [%0], {%1, %2, %3, %4};"
                 :: "l"(p), "f"(a), "f"(b), "f"(c), "f"(d) : "memory");
}

__global__ __launch_bounds__(NTH, 1)
void p2g_kernel(const float* __restrict__ pos,
                const float* __restrict__ feat,
                const float* __restrict__ W1,
                const float* __restrict__ b1,
                const float* __restrict__ lng,
                const float* __restrict__ lnb,
                const float* __restrict__ W2,
                const float* __restrict__ b2,
                const int*   __restrict__ ax1p,
                const int*   __restrict__ ax2p) {
    extern __shared__ float sm[];
    int* sFlat = (int*)&sm[OFL];
    const int tid  = threadIdx.x;
    const int base = blockIdx.x * BLK;

    // ---- stage weights (W2 duplicated), biases, freq table ----
    {
        const float4* w1v = (const float4*)W1;
        float4* d1 = (float4*)&sm[OW1];
#pragma unroll
        for (int i = 0; i < 6; ++i) d1[tid + i * NTH] = w1v[tid + i * NTH];
        if (tid < 3328 - 6 * NTH) d1[tid + 6 * NTH] = w1v[tid + 6 * NTH];

        float2* d2 = (float2*)&sm[OW2D];
#pragma unroll
        for (int i = 0; i < 8; ++i) {
            float v = W2[tid + i * NTH];
            d2[tid + i * NTH] = make_float2(v, v);
        }
        if (tid < 64) {
            sm[OB1 + tid] = b1[tid];
            sm[OG  + tid] = lng[tid];
            sm[OB  + tid] = lnb[tid];
            sm[OB2 + tid] = b2[tid];
        }
        if (tid < 32) sm[OFQ + tid] = exp2f((float)tid * 0.03125f) * 1.57079632679489662f;
    }

    // ---- per-point data: 2 threads per point ----
    const int p   = tid & 255;
    const int pg  = min(base + p, NPTS - 1);
    float pd[3];
    pd[0] = pos[pg * 3 + 0];
    pd[1] = pos[pg * 3 + 1];
    pd[2] = pos[pg * 3 + 2];
    float freg[16];
    {
        const float4* fv = (const float4*)(feat + pg * 16);
#pragma unroll
        for (int i = 0; i < 4; ++i) {
            float4 t = fv[i];
            freg[4 * i + 0] = t.x; freg[4 * i + 1] = t.y;
            freg[4 * i + 2] = t.z; freg[4 * i + 3] = t.w;
        }
    }
    if (tid < 256) {
        int a1 = *ax1p, a2 = *ax2p;
        float n1 = fminf(fmaxf((pd[a1] + 1.0f) * 0.5f, 0.0f), 1.0f);
        float n2 = fminf(fmaxf((pd[a2] + 1.0f) * 0.5f, 0.0f), 1.0f);
        int i1 = min(max((int)floorf(n1 * (float)GRID_H), 0), GRID_H - 1);
        int i2 = min(max((int)floorf(n2 * (float)GRID_W), 0), GRID_W - 1);
        sFlat[tid] = i1 * GRID_W + i2;
    }

    const int ptg = tid >> 3;     // 0..63 : points ptg*4 .. +3
    const int chg = tid & 7;      // 0..7  : channels chg*8 .. +7
    const int hhalf = tid >> 8;   // X-build row split

    unsigned long long acc[4][4];   // [pt][chpair]
#pragma unroll
    for (int a = 0; a < 4; ++a)
#pragma unroll
        for (int b = 0; b < 4; ++b) acc[a][b] = 0ull;

    __syncthreads();

    // ================= GEMM1: 8 chunks of K=26 =================
#pragma unroll 1
    for (int c = 0; c < 8; ++c) {
        const int k0 = c * KC;
        // build X chunk, duplicated: X_dup[i][2p] = X_dup[i][2p+1]
#pragma unroll 1
        for (int i = hhalf; i < KC; i += 2) {
            int k = k0 + i;
            float v;
            if (k < 16) {
                v = freg[k];
            } else {
                int j = k - 16;
                float arg = pd[j >> 6] * sm[OFQ + (j & 31)];
                v = (j & 32) ? __cosf(arg) : __sinf(arg);
            }
            *(float2*)&sm[OXD + i * 512 + 2 * p] = make_float2(v, v);
        }
        __syncthreads();

#pragma unroll 13
        for (int i = 0; i < KC; ++i) {
            const float* xr = &sm[OXD + i * 512 + ptg * 8];
            ulonglong2 xa = *(const ulonglong2*)xr;       // dup(p0), dup(p1)
            ulonglong2 xb = *(const ulonglong2*)(xr + 4); // dup(p2), dup(p3)
            unsigned long long xp[4] = {xa.x, xa.y, xb.x, xb.y};
            const float* wr = &sm[OW1 + (k0 + i) * 64 + chg * 8];
            ulonglong2 wa = *(const ulonglong2*)wr;       // (w0,w1),(w2,w3)
            ulonglong2 wb = *(const ulonglong2*)(wr + 4); // (w4,w5),(w6,w7)
            unsigned long long wp[4] = {wa.x, wa.y, wb.x, wb.y};
#pragma unroll
            for (int a = 0; a < 4; ++a)
#pragma unroll
                for (int b = 0; b < 4; ++b) fma2(acc[a][b], xp[a], wp[b]);
        }
        __syncthreads();
    }

    // ---- bias + LayerNorm + exact GELU in registers (8-lane shuffles) ----
    {
        float h[4][8];
#pragma unroll
        for (int a = 0; a < 4; ++a)
#pragma unroll
            for (int cp = 0; cp < 4; ++cp) {
                float2 t = up2(acc[a][cp]);
                h[a][2 * cp]     = t.x + sm[OB1 + chg * 8 + 2 * cp];
                h[a][2 * cp + 1] = t.y + sm[OB1 + chg * 8 + 2 * cp + 1];
            }
        float s[4], s2[4];
#pragma unroll
        for (int a = 0; a < 4; ++a) {
            s[a] = 0.0f; s2[a] = 0.0f;
#pragma unroll
            for (int j = 0; j < 8; ++j) { s[a] += h[a][j]; s2[a] += h[a][j] * h[a][j]; }
        }
#pragma unroll
        for (int o = 1; o < 8; o <<= 1) {
#pragma unroll
            for (int a = 0; a < 4; ++a) {
                s[a]  += __shfl_xor_sync(0xFFFFFFFF, s[a],  o);
                s2[a] += __shfl_xor_sync(0xFFFFFFFF, s2[a], o);
            }
        }
        float gl[8], bl[8];
#pragma unroll
        for (int j = 0; j < 8; ++j) {
            gl[j] = sm[OG + chg * 8 + j];
            bl[j] = sm[OB + chg * 8 + j];
        }
#pragma unroll
        for (int a = 0; a < 4; ++a) {
            float mu   = s[a] * (1.0f / 64.0f);
            float var  = s2[a] * (1.0f / 64.0f) - mu * mu;
            float rstd = rsqrtf(var + 1e-5f);
#pragma unroll
            for (int j = 0; j < 8; ++j) {
                float v = (h[a][j] - mu) * rstd * gl[j] + bl[j];
                h[a][j] = 0.5f * v * (1.0f + erff(v * 0.70710678118654752f));
            }
        }
        // store H [ch][pt] stride HP
#pragma unroll
        for (int j = 0; j < 8; ++j) {
            int ch = chg * 8 + j;
            float4 o = {h[0][j], h[1][j], h[2][j], h[3][j]};
            *(float4*)&sm[OH + ch * HP + ptg * 4] = o;
        }
    }
    __syncthreads();

    // ================= GEMM2: lanes = point pairs, W2 pre-duplicated =========
    unsigned long long acc2[2][8];   // [ptpair][ch]
#pragma unroll
    for (int a = 0; a < 2; ++a)
#pragma unroll
        for (int b = 0; b < 8; ++b) acc2[a][b] = 0ull;

#pragma unroll 8
    for (int k = 0; k < 64; ++k) {
        ulonglong2 xv = *(const ulonglong2*)&sm[OH + k * HP + ptg * 4]; // (p0,p1),(p2,p3)
        const float* wr = &sm[OW2D + k * 128 + chg * 16];
        ulonglong2 w0 = *(const ulonglong2*)wr;
        ulonglong2 w1 = *(const ulonglong2*)(wr + 4);
        ulonglong2 w2 = *(const ulonglong2*)(wr + 8);
        ulonglong2 w3 = *(const ulonglong2*)(wr + 12);
        unsigned long long wd[8] = {w0.x, w0.y, w1.x, w1.y, w2.x, w2.y, w3.x, w3.y};
#pragma unroll
        for (int b = 0; b < 8; ++b) {
            fma2(acc2[0][b], xv.x, wd[b]);
            fma2(acc2[1][b], xv.y, wd[b]);
        }
    }

    // ---- scatter: red.v4 into cell-major scratch ----
    float bias[8];
#pragma unroll
    for (int b = 0; b < 8; ++b) bias[b] = sm[OB2 + chg * 8 + b];

#pragma unroll
    for (int pl = 0; pl < 4; ++pl) {
        int pG = base + ptg * 4 + pl;
        if (pG < NPTS) {
            int fl = sFlat[ptg * 4 + pl];
            float* dst = &g_accum[fl * 64 + chg * 8];
            int pr = pl >> 1;
            bool hi = pl & 1;
            float v[8];
#pragma unroll
            for (int b = 0; b < 8; ++b) {
                float2 t = up2(acc2[pr][b]);
                v[b] = (hi ? t.y : t.x) + bias[b];
            }
            red4(dst,     v[0], v[1], v[2], v[3]);
            red4(dst + 4, v[4], v[5], v[6], v[7]);
            if (chg == 0) atomicAdd(&g_counts[fl], 1.0f);
        }
    }
}

// transpose [cell][ch] -> [ch][cell], mean-divide, and re-zero the scratch
__global__ __launch_bounds__(256)
void finalize_kernel(float* __restrict__ out) {
    __shared__ float tile[64][65];
    __shared__ float cnt[64];
    const int tid = threadIdx.x;
    const int cell0 = blockIdx.x * 64;

#pragma unroll
    for (int it = 0; it < 4; ++it) {
        int lin = it * 256 + tid;            // 0..1023, float4 granules
        float4* src = (float4*)&g_accum[cell0 * 64] + lin;
        float4 v = *src;
        int row = lin >> 4, col4 = (lin & 15) * 4;
        tile[row][col4 + 0] = v.x;
        tile[row][col4 + 1] = v.y;
        tile[row][col4 + 2] = v.z;
        tile[row][col4 + 3] = v.w;
        *src = make_float4(0.0f, 0.0f, 0.0f, 0.0f);   // re-zero for next launch
    }
    if (tid < 64) {
        cnt[tid] = 1.0f / fmaxf(g_counts[cell0 + tid], 1.0f);
        g_counts[cell0 + tid] = 0.0f;                  // re-zero
    }
    __syncthreads();

#pragma unroll
    for (int it = 0; it < 4; ++it) {
        int lin = it * 256 + tid;            // 0..1023
        int ch = lin >> 4, cl4 = (lin & 15) * 4;
        float4 o;
        o.x = tile[cl4 + 0][ch] * cnt[cl4 + 0];
        o.y = tile[cl4 + 1][ch] * cnt[cl4 + 1];
        o.z = tile[cl4 + 2][ch] * cnt[cl4 + 2];
        o.w = tile[cl4 + 3][ch] * cnt[cl4 + 3];
        *(float4*)&out[ch * NCELL + cell0 + cl4] = o;
    }
}

extern "C" void kernel_launch(void* const* d_in, const int* in_sizes, int n_in,
                              void* d_out, int out_size) {
    const float* pos  = (const float*)d_in[0];
    const float* feat = (const float*)d_in[1];
    const float* W1   = (const float*)d_in[2];
    const float* b1   = (const float*)d_in[3];
    const float* lng  = (const float*)d_in[4];
    const float* lnb  = (const float*)d_in[5];
    const float* W2   = (const float*)d_in[6];
    const float* b2   = (const float*)d_in[7];
    const int*   ax1  = (const int*)d_in[8];
    const int*   ax2  = (const int*)d_in[9];
    float* out = (float*)d_out;

    cudaFuncSetAttribute(p2g_kernel, cudaFuncAttributeMaxDynamicSharedMemorySize, SMB);

    // g_accum / g_counts start zeroed (device globals) and finalize_kernel
    // re-zeroes them each call, so no separate zero pass is needed.
    p2g_kernel<<<NBLK, NTH, SMB>>>(pos, feat, W1, b1, lng, lnb, W2, b2, ax1, ax2);
    finalize_kernel<<<NCELL / 64, 256>>>(out);
}

// round 7
// speedup vs baseline: 1.5083x; 1.5083x over previous
#include <cuda_runtime.h>
#include <cuda_bf16.h>

#define NPTS    500000
#define C_OUT   64
#define GRID_H  256
#define GRID_W  256
#define NCELL   (GRID_H * GRID_W)
#define BLK     256
#define NBLK    ((NPTS + BLK - 1) / BLK)

// shared float offsets
#define OW1  0            // 208*64 = 13312
#define OW2  13312        // 64*64  = 4096
#define OMP  17408        // 64 * (freq, phase) pairs = 128
#define OB1  17536
#define OG   17600
#define OB   17664
#define OB2  17728
#define SMF  17792
#define SMB  (SMF * 4)    // 71168 B -> 2 CTAs/SM

__device__ float g_accum[NCELL * C_OUT];   // cell-major scratch [cell][ch]
__device__ float g_counts[NCELL];

__device__ __forceinline__ void fma2(unsigned long long& d, unsigned long long a,
                                     unsigned long long b) {
    asm("fma.rn.f32x2 %0, %1, %2, %0;" : "+l"(d) : "l"(a), "l"(b));
}
__device__ __forceinline__ unsigned long long dup2(float v) {
    unsigned long long r; asm("mov.b64 %0, {%1, %1};" : "=l"(r) : "f"(v)); return r;
}
__device__ __forceinline__ unsigned long long pk(float x, float y) {
    unsigned long long r; asm("mov.b64 %0, {%1, %2};" : "=l"(r) : "f"(x), "f"(y)); return r;
}
__device__ __forceinline__ float2 up2(unsigned long long a) {
    float2 r; asm("mov.b64 {%0, %1}, %2;" : "=f"(r.x), "=f"(r.y) : "l"(a)); return r;
}
__device__ __forceinline__ void red4(float* p, float a, float b, float c, float d) {
    asm volatile("red.global.add.v4.f32 [%0], {%1, %2, %3, %4};"
                 :: "l"(p), "f"(a), "f"(b), "f"(c), "f"(d) : "memory");
}

// one k-step of GEMM1: 64 channels via 16 broadcast LDS.128 + 32 FFMA2
#define MAC64(WBASE, XD)                                           \
    {                                                              \
        const ulonglong2* _wv = (const ulonglong2*)(WBASE);        \
        _Pragma("unroll")                                          \
        for (int _c = 0; _c < 16; ++_c) {                          \
            ulonglong2 _w = _wv[_c];                               \
            fma2(acc[2 * _c],     (XD), _w.x);                     \
            fma2(acc[2 * _c + 1], (XD), _w.y);                     \
        }                                                          \
    }

__global__ __launch_bounds__(256, 2)
void p2g_kernel(const float* __restrict__ pos,
                const float* __restrict__ feat,
                const float* __restrict__ W1,
                const float* __restrict__ b1,
                const float* __restrict__ lng,
                const float* __restrict__ lnb,
                const float* __restrict__ W2,
                const float* __restrict__ b2,
                const int*   __restrict__ ax1p,
                const int*   __restrict__ ax2p) {
    extern __shared__ float sm[];
    const int tid  = threadIdx.x;
    const int base = blockIdx.x * BLK;

    // ---- stage weights + tables (one barrier total) ----
    {
        const float4* w1v = (const float4*)W1;
        float4* d1 = (float4*)&sm[OW1];
#pragma unroll
        for (int i = 0; i < 13; ++i) d1[tid + i * 256] = w1v[tid + i * 256];
        const float4* w2v = (const float4*)W2;
        float4* d2 = (float4*)&sm[OW2];
#pragma unroll
        for (int i = 0; i < 4; ++i) d2[tid + i * 256] = w2v[tid + i * 256];
        if (tid < 64) {
            int f = tid & 31, t = tid >> 5;
            sm[OMP + 2 * tid]     = exp2f((float)f * 0.03125f) * 1.57079632679489662f;
            sm[OMP + 2 * tid + 1] = t ? 1.57079632679489662f : 0.0f;
            sm[OB1 + tid] = b1[tid];
            sm[OG  + tid] = lng[tid];
            sm[OB  + tid] = lnb[tid];
            sm[OB2 + tid] = b2[tid];
        }
    }

    // ---- per-thread point ----
    const bool valid = (base + tid) < NPTS;
    const int  pg    = valid ? (base + tid) : (NPTS - 1);
    float pd0 = pos[pg * 3 + 0];
    float pd1 = pos[pg * 3 + 1];
    float pd2 = pos[pg * 3 + 2];
    float fr[16];
    {
        const float4* fv = (const float4*)(feat + pg * 16);
#pragma unroll
        for (int i = 0; i < 4; ++i) {
            float4 t = fv[i];
            fr[4 * i + 0] = t.x; fr[4 * i + 1] = t.y;
            fr[4 * i + 2] = t.z; fr[4 * i + 3] = t.w;
        }
    }
    int fl;
    {
        int a1 = *ax1p, a2 = *ax2p;
        float v1 = (a1 == 0) ? pd0 : ((a1 == 1) ? pd1 : pd2);
        float v2 = (a2 == 0) ? pd0 : ((a2 == 1) ? pd1 : pd2);
        float n1 = fminf(fmaxf((v1 + 1.0f) * 0.5f, 0.0f), 1.0f);
        float n2 = fminf(fmaxf((v2 + 1.0f) * 0.5f, 0.0f), 1.0f);
        int i1 = min(max((int)floorf(n1 * (float)GRID_H), 0), GRID_H - 1);
        int i2 = min(max((int)floorf(n2 * (float)GRID_W), 0), GRID_W - 1);
        fl = i1 * GRID_W + i2;
    }

    unsigned long long acc[32];
#pragma unroll
    for (int i = 0; i < 32; ++i) acc[i] = 0ull;

    __syncthreads();

    // ================= GEMM1: features (k=0..15) =================
#pragma unroll
    for (int k = 0; k < 16; ++k) {
        unsigned long long xd = dup2(fr[k]);
        MAC64(&sm[OW1 + k * 64], xd);
    }

    // ================= GEMM1: PE dims (k=16..207) =================
    {
        float p = pd0;
        const float* wr0 = &sm[OW1 + 16 * 64];
        const float* wr1 = &sm[OW1 + 80 * 64];
        const float* wr2 = &sm[OW1 + 144 * 64];
#pragma unroll 2
        for (int r = 0; r < 64; ++r) {
            float2 mp = *(const float2*)&sm[OMP + 2 * r];
            unsigned long long xd = dup2(__sinf(fmaf(pd0, mp.x, mp.y)));
            MAC64(wr0 + r * 64, xd);
        }
#pragma unroll 2
        for (int r = 0; r < 64; ++r) {
            float2 mp = *(const float2*)&sm[OMP + 2 * r];
            unsigned long long xd = dup2(__sinf(fmaf(pd1, mp.x, mp.y)));
            MAC64(wr1 + r * 64, xd);
        }
#pragma unroll 2
        for (int r = 0; r < 64; ++r) {
            float2 mp = *(const float2*)&sm[OMP + 2 * r];
            unsigned long long xd = dup2(__sinf(fmaf(pd2, mp.x, mp.y)));
            MAC64(wr2 + r * 64, xd);
        }
        (void)p;
    }

    // ---- bias + LayerNorm + exact GELU, all in registers ----
    {
        float s = 0.0f, s2 = 0.0f;
#pragma unroll
        for (int i = 0; i < 32; ++i) {
            float2 t = up2(acc[i]);
            t.x += sm[OB1 + 2 * i];
            t.y += sm[OB1 + 2 * i + 1];
            s  += t.x + t.y;
            s2 += t.x * t.x + t.y * t.y;
            acc[i] = pk(t.x, t.y);
        }
        float mu   = s * (1.0f / 64.0f);
        float var  = s2 * (1.0f / 64.0f) - mu * mu;
        float rstd = rsqrtf(var + 1e-5f);
#pragma unroll
        for (int i = 0; i < 32; ++i) {
            float2 t = up2(acc[i]);
            float vx = (t.x - mu) * rstd * sm[OG + 2 * i]     + sm[OB + 2 * i];
            float vy = (t.y - mu) * rstd * sm[OG + 2 * i + 1] + sm[OB + 2 * i + 1];
            vx = 0.5f * vx * (1.0f + erff(vx * 0.70710678118654752f));
            vy = 0.5f * vy * (1.0f + erff(vy * 0.70710678118654752f));
            acc[i] = pk(vx, vy);
        }
    }

    // ================= GEMM2 + scatter: two 32-channel passes =================
#pragma unroll
    for (int ph = 0; ph < 2; ++ph) {
        unsigned long long a2[16];
#pragma unroll
        for (int i = 0; i < 16; ++i) a2[i] = 0ull;

#pragma unroll
        for (int i = 0; i < 32; ++i) {          // k pair = (2i, 2i+1)
            float2 t = up2(acc[i]);
            unsigned long long x0 = dup2(t.x);
            unsigned long long x1 = dup2(t.y);
            const ulonglong2* w0 = (const ulonglong2*)&sm[OW2 + (2 * i) * 64 + ph * 32];
            const ulonglong2* w1 = (const ulonglong2*)&sm[OW2 + (2 * i + 1) * 64 + ph * 32];
#pragma unroll
            for (int c = 0; c < 8; ++c) {
                ulonglong2 wa = w0[c];
                fma2(a2[2 * c],     x0, wa.x);
                fma2(a2[2 * c + 1], x0, wa.y);
            }
#pragma unroll
            for (int c = 0; c < 8; ++c) {
                ulonglong2 wb = w1[c];
                fma2(a2[2 * c],     x1, wb.x);
                fma2(a2[2 * c + 1], x1, wb.y);
            }
        }

        if (valid) {
            float* dst = &g_accum[fl * 64 + ph * 32];
#pragma unroll
            for (int q = 0; q < 4; ++q) {
                float2 t0 = up2(a2[2 * q]);
                float2 t1 = up2(a2[2 * q + 1]);
                red4(dst + 4 * q,
                     t0.x + sm[OB2 + ph * 32 + 4 * q + 0],
                     t0.y + sm[OB2 + ph * 32 + 4 * q + 1],
                     t1.x + sm[OB2 + ph * 32 + 4 * q + 2],
                     t1.y + sm[OB2 + ph * 32 + 4 * q + 3]);
            }
#pragma unroll
            for (int q = 4; q < 8; ++q) {
                float2 t0 = up2(a2[2 * q]);
                float2 t1 = up2(a2[2 * q + 1]);
                red4(dst + 4 * q,
                     t0.x + sm[OB2 + ph * 32 + 4 * q + 0],
                     t0.y + sm[OB2 + ph * 32 + 4 * q + 1],
                     t1.x + sm[OB2 + ph * 32 + 4 * q + 2],
                     t1.y + sm[OB2 + ph * 32 + 4 * q + 3]);
            }
        }
    }
    if (valid) atomicAdd(&g_counts[fl], 1.0f);
}

// transpose [cell][ch] -> [ch][cell], mean-divide, re-zero scratch
__global__ __launch_bounds__(256)
void finalize_kernel(float* __restrict__ out) {
    __shared__ float tile[64][65];
    __shared__ float cnt[64];
    const int tid = threadIdx.x;
    const int cell0 = blockIdx.x * 64;

#pragma unroll
    for (int it = 0; it < 4; ++it) {
        int lin = it * 256 + tid;
        float4* src = (float4*)&g_accum[cell0 * 64] + lin;
        float4 v = *src;
        int row = lin >> 4, col4 = (lin & 15) * 4;
        tile[row][col4 + 0] = v.x;
        tile[row][col4 + 1] = v.y;
        tile[row][col4 + 2] = v.z;
        tile[row][col4 + 3] = v.w;
        *src = make_float4(0.0f, 0.0f, 0.0f, 0.0f);
    }
    if (tid < 64) {
        cnt[tid] = 1.0f / fmaxf(g_counts[cell0 + tid], 1.0f);
        g_counts[cell0 + tid] = 0.0f;
    }
    __syncthreads();

#pragma unroll
    for (int it = 0; it < 4; ++it) {
        int lin = it * 256 + tid;
        int ch = lin >> 4, cl4 = (lin & 15) * 4;
        float4 o;
        o.x = tile[cl4 + 0][ch] * cnt[cl4 + 0];
        o.y = tile[cl4 + 1][ch] * cnt[cl4 + 1];
        o.z = tile[cl4 + 2][ch] * cnt[cl4 + 2];
        o.w = tile[cl4 + 3][ch] * cnt[cl4 + 3];
        *(float4*)&out[ch * NCELL + cell0 + cl4] = o;
    }
}

extern "C" void kernel_launch(void* const* d_in, const int* in_sizes, int n_in,
                              void* d_out, int out_size) {
    const float* pos  = (const float*)d_in[0];
    const float* feat = (const float*)d_in[1];
    const float* W1   = (const float*)d_in[2];
    const float* b1   = (const float*)d_in[3];
    const float* lng  = (const float*)d_in[4];
    const float* lnb  = (const float*)d_in[5];
    const float* W2   = (const float*)d_in[6];
    const float* b2   = (const float*)d_in[7];
    const int*   ax1  = (const int*)d_in[8];
    const int*   ax2  = (const int*)d_in[9];
    float* out = (float*)d_out;

    cudaFuncSetAttribute(p2g_kernel, cudaFuncAttributeMaxDynamicSharedMemorySize, SMB);

    // g_accum / g_counts start zeroed (device globals); finalize_kernel
    // re-zeroes them each call, so no separate zero pass is needed.
    p2g_kernel<<<NBLK, 256, SMB>>>(pos, feat, W1, b1, lng, lnb, W2, b2, ax1, ax2);
    finalize_kernel<<<NCELL / 64, 256>>>(out);
}